// round 4
// baseline (speedup 1.0000x reference)
#include <cuda_runtime.h>
#include <cuda_bf16.h>
#include <cstdint>

#define BATCH 16
#define SEQ   2048
#define DIM   128
#define BM    64
#define BN    64
#define KTILES (SEQ / BN)
#define NTHREADS 128

// bf16 tiles: 64 rows x 128 bf16 = 256 B/row, XOR swizzle on 16B chunks.
#define TS      16384
#define SM_Q_HI 0
#define SM_Q_LO 16384
#define SM_K_HI 32768
#define SM_K_LO 49152
#define SM_V_HI 65536
#define SM_V_LO 81920
#define SM_SC   98304                    // scale [64][68] f32
#define SM_TOTAL (SM_SC + 64 * 68 * 4)   // 115712 B = 113 KB -> 2 CTAs/SM

__device__ __forceinline__ uint32_t smem_u32(const void* p) {
    uint32_t a;
    asm("{ .reg .u64 t; cvta.to.shared.u64 t, %1; cvt.u32.u64 %0, t; }" : "=r"(a) : "l"(p));
    return a;
}
// byte offset of 8-byte half-chunk (r, c4) in a swizzled 256B-stride tile
__device__ __forceinline__ uint32_t swz(int r, int c4) {
    return (uint32_t)(r * 256 + ((((c4 >> 1) ^ (r & 7)) << 4) | ((c4 & 1) << 3)));
}
__device__ __forceinline__ void ldsm_x4(uint32_t* r, uint32_t a) {
    asm volatile("ldmatrix.sync.aligned.m8n8.x4.shared.b16 {%0,%1,%2,%3}, [%4];"
        : "=r"(r[0]), "=r"(r[1]), "=r"(r[2]), "=r"(r[3]) : "r"(a));
}
__device__ __forceinline__ void ldsm_x4_t(uint32_t* r, uint32_t a) {
    asm volatile("ldmatrix.sync.aligned.m8n8.x4.trans.shared.b16 {%0,%1,%2,%3}, [%4];"
        : "=r"(r[0]), "=r"(r[1]), "=r"(r[2]), "=r"(r[3]) : "r"(a));
}
__device__ __forceinline__ void mma_bf16(float* c, const uint32_t* a, uint32_t b0, uint32_t b1) {
    asm volatile("mma.sync.aligned.m16n8k16.row.col.f32.bf16.bf16.f32 "
        "{%0,%1,%2,%3}, {%4,%5,%6,%7}, {%8,%9}, {%0,%1,%2,%3};"
        : "+f"(c[0]), "+f"(c[1]), "+f"(c[2]), "+f"(c[3])
        : "r"(a[0]), "r"(a[1]), "r"(a[2]), "r"(a[3]), "r"(b0), "r"(b1));
}
__device__ __forceinline__ uint32_t pack_bf16(float lo, float hi) {
    __nv_bfloat162 t = __floats2bfloat162_rn(lo, hi);
    return *reinterpret_cast<uint32_t*>(&t);
}
__device__ __forceinline__ void cvt_split(float4 v, uint2& hi, uint2& lo) {
    __nv_bfloat162 h01 = __floats2bfloat162_rn(v.x, v.y);
    __nv_bfloat162 h23 = __floats2bfloat162_rn(v.z, v.w);
    float rx = v.x - __bfloat162float(h01.x);
    float ry = v.y - __bfloat162float(h01.y);
    float rz = v.z - __bfloat162float(h23.x);
    float rw = v.w - __bfloat162float(h23.y);
    __nv_bfloat162 l01 = __floats2bfloat162_rn(rx, ry);
    __nv_bfloat162 l23 = __floats2bfloat162_rn(rz, rw);
    hi = make_uint2(*reinterpret_cast<uint32_t*>(&h01), *reinterpret_cast<uint32_t*>(&h23));
    lo = make_uint2(*reinterpret_cast<uint32_t*>(&l01), *reinterpret_cast<uint32_t*>(&l23));
}
// FFMA-pipe exp (no MUFU), x <= 0; fexp(0) == 1.0f exactly
__device__ __forceinline__ float fexp(float x) {
    float t = fmaxf(x * 1.4426950408889634f, -126.0f);
    float z = __fadd_rn(t, 12582912.0f);
    int   n = __float_as_int(z) - 0x4B400000;
    float f = t - (z - 12582912.0f);
    float p = 0.0013333558f;
    p = fmaf(p, f, 0.0096181291f);
    p = fmaf(p, f, 0.0555041086f);
    p = fmaf(p, f, 0.2402265069f);
    p = fmaf(p, f, 0.6931471806f);
    p = fmaf(p, f, 1.0f);
    return __int_as_float(__float_as_int(p) + (n << 23));
}
__device__ __forceinline__ void cp_async16(uint32_t dst, const void* src) {
    asm volatile("cp.async.ca.shared.global [%0], [%1], 16;" :: "r"(dst), "l"(src));
}

__global__ __launch_bounds__(NTHREADS, 2)
void attn_mma_kernel(const float* __restrict__ Q, const float* __restrict__ K,
                     const float* __restrict__ V, const float* __restrict__ scale,
                     float* __restrict__ Out)
{
    extern __shared__ char smem[];
    const uint32_t sb = smem_u32(smem);
    float* scs = (float*)(smem + SM_SC);

    const int tid  = threadIdx.x;
    const int wid  = tid >> 5;
    const int lane = tid & 31;
    const int g    = lane >> 2;
    const int t4   = lane & 3;
    const int wr   = wid * 16;
    const int q0   = blockIdx.x * BM;
    const int b    = blockIdx.y;
    const int m7   = lane & 7;

    const float* Qb = Q + (size_t)b * SEQ * DIM;
    const float* Kb = K + (size_t)b * SEQ * DIM;
    const float* Vb = V + (size_t)b * SEQ * DIM;

    // ---- stage Q tile once: f32 -> bf16 hi/lo, swizzled ----
    for (int i = tid; i < BM * 32; i += NTHREADS) {
        int r = i >> 5, c4 = i & 31;
        float4 v = *(const float4*)(Qb + (size_t)(q0 + r) * DIM + c4 * 4);
        uint2 hi, lo; cvt_split(v, hi, lo);
        uint32_t so = swz(r, c4);
        *(uint2*)(smem + SM_Q_HI + so) = hi;
        *(uint2*)(smem + SM_Q_LO + so) = lo;
    }

    // per-lane ldmatrix bases (swizzled layout)
    const uint32_t hcA = (lane >> 4) & 1;                 // Q / A fragment
    const uint32_t hcB = (lane >> 3) & 1;                 // K / B fragment
    const uint32_t hcV = (lane >> 4) & 1;                 // V / B fragment (trans)
    const uint32_t qrow  = (uint32_t)(wr + m7 + ((lane >> 3) & 1) * 8);
    const uint32_t krowl = (uint32_t)(m7 + ((lane >> 4) & 1) * 8);
    const uint32_t vrowl = (uint32_t)(lane & 15);
    const uint32_t qbase = sb + qrow * 256;               // + SM_Q_HI/LO
    const uint32_t kbase = sb + krowl * 256;
    const uint32_t vbase = sb + vrowl * 256;

    float o[16][4];
    #pragma unroll
    for (int j = 0; j < 16; j++)
        { o[j][0] = 0.f; o[j][1] = 0.f; o[j][2] = 0.f; o[j][3] = 0.f; }
    float m0 = -1e30f, m1 = -1e30f, l0 = 0.f, l1 = 0.f;

    for (int kt = 0; kt < KTILES; kt++) {
        const int k0 = kt * BN;
        __syncthreads();

        // ---- scale tile via cp.async (f32, no conversion) ----
        for (int i = tid; i < BM * 16; i += NTHREADS) {
            int r = i >> 4, c4 = i & 15;
            cp_async16(sb + SM_SC + (uint32_t)(r * 272 + c4 * 16),
                       scale + (size_t)(q0 + r) * SEQ + k0 + c4 * 4);
        }
        // ---- K, V tiles: f32 -> bf16 hi/lo, swizzled ----
        for (int i = tid; i < BN * 32; i += NTHREADS) {
            int r = i >> 5, c4 = i & 31;
            float4 kv = *(const float4*)(Kb + (size_t)(k0 + r) * DIM + c4 * 4);
            float4 vv = *(const float4*)(Vb + (size_t)(k0 + r) * DIM + c4 * 4);
            uint2 hi, lo;
            uint32_t so = swz(r, c4);
            cvt_split(kv, hi, lo);
            *(uint2*)(smem + SM_K_HI + so) = hi;
            *(uint2*)(smem + SM_K_LO + so) = lo;
            cvt_split(vv, hi, lo);
            *(uint2*)(smem + SM_V_HI + so) = hi;
            *(uint2*)(smem + SM_V_LO + so) = lo;
        }
        asm volatile("cp.async.wait_all;" ::: "memory");
        __syncthreads();

        // ---- S = (Q K^T), bf16 3-product split ----
        float s[8][4];
        #pragma unroll
        for (int j = 0; j < 8; j++)
            { s[j][0] = 0.f; s[j][1] = 0.f; s[j][2] = 0.f; s[j][3] = 0.f; }

        #pragma unroll
        for (int kc = 0; kc < 8; kc++) {
            uint32_t aoff = ((2u * kc + hcA) ^ m7) << 4;
            uint32_t ah[4], al[4];
            ldsm_x4(ah, qbase + SM_Q_HI + aoff);
            ldsm_x4(al, qbase + SM_Q_LO + aoff);
            uint32_t boff = ((2u * kc + hcB) ^ m7) << 4;
            #pragma unroll
            for (int jp = 0; jp < 4; jp++) {
                uint32_t ka = kbase + jp * 4096u + boff;
                uint32_t bh[4], bl[4];
                ldsm_x4(bh, ka + SM_K_HI);
                ldsm_x4(bl, ka + SM_K_LO);
                mma_bf16(s[2*jp],   ah, bh[0], bh[1]);
                mma_bf16(s[2*jp],   ah, bl[0], bl[1]);
                mma_bf16(s[2*jp],   al, bh[0], bh[1]);
                mma_bf16(s[2*jp+1], ah, bh[2], bh[3]);
                mma_bf16(s[2*jp+1], ah, bl[2], bl[3]);
                mma_bf16(s[2*jp+1], al, bh[2], bh[3]);
            }
        }

        // ---- scale multiply + online softmax ----
        const float* sc0 = scs + (wr + g) * 68;
        const float* sc1 = sc0 + 8 * 68;
        float mx0 = -1e30f, mx1 = -1e30f;
        #pragma unroll
        for (int j = 0; j < 8; j++) {
            float2 a = *(const float2*)(sc0 + 8 * j + 2 * t4);
            float2 c = *(const float2*)(sc1 + 8 * j + 2 * t4);
            s[j][0] *= a.x; s[j][1] *= a.y;
            s[j][2] *= c.x; s[j][3] *= c.y;
            mx0 = fmaxf(mx0, fmaxf(s[j][0], s[j][1]));
            mx1 = fmaxf(mx1, fmaxf(s[j][2], s[j][3]));
        }
        mx0 = fmaxf(mx0, __shfl_xor_sync(0xffffffffu, mx0, 1));
        mx0 = fmaxf(mx0, __shfl_xor_sync(0xffffffffu, mx0, 2));
        mx1 = fmaxf(mx1, __shfl_xor_sync(0xffffffffu, mx1, 1));
        mx1 = fmaxf(mx1, __shfl_xor_sync(0xffffffffu, mx1, 2));

        float mn0 = fmaxf(m0, mx0), mn1 = fmaxf(m1, mx1);
        float a0 = fexp(m0 - mn0),  a1 = fexp(m1 - mn1);
        float sum0 = 0.f, sum1 = 0.f;
        #pragma unroll
        for (int j = 0; j < 8; j++) {
            s[j][0] = fexp(s[j][0] - mn0); sum0 += s[j][0];
            s[j][1] = fexp(s[j][1] - mn0); sum0 += s[j][1];
            s[j][2] = fexp(s[j][2] - mn1); sum1 += s[j][2];
            s[j][3] = fexp(s[j][3] - mn1); sum1 += s[j][3];
        }
        sum0 += __shfl_xor_sync(0xffffffffu, sum0, 1);
        sum0 += __shfl_xor_sync(0xffffffffu, sum0, 2);
        sum1 += __shfl_xor_sync(0xffffffffu, sum1, 1);
        sum1 += __shfl_xor_sync(0xffffffffu, sum1, 2);
        l0 = l0 * a0 + sum0; m0 = mn0;
        l1 = l1 * a1 + sum1; m1 = mn1;
        if (a0 != 1.0f || a1 != 1.0f) {
            #pragma unroll
            for (int j = 0; j < 16; j++) {
                o[j][0] *= a0; o[j][1] *= a0;
                o[j][2] *= a1; o[j][3] *= a1;
            }
        }

        // ---- O += P V, bf16 3-product split ----
        #pragma unroll
        for (int c = 0; c < 4; c++) {
            uint32_t ph[4], pl[4];
            {
                __nv_bfloat162 h; float r0, r1;
                h = __floats2bfloat162_rn(s[2*c][0], s[2*c][1]); ph[0] = *(uint32_t*)&h;
                r0 = s[2*c][0] - __bfloat162float(h.x); r1 = s[2*c][1] - __bfloat162float(h.y);
                pl[0] = pack_bf16(r0, r1);
                h = __floats2bfloat162_rn(s[2*c][2], s[2*c][3]); ph[1] = *(uint32_t*)&h;
                r0 = s[2*c][2] - __bfloat162float(h.x); r1 = s[2*c][3] - __bfloat162float(h.y);
                pl[1] = pack_bf16(r0, r1);
                h = __floats2bfloat162_rn(s[2*c+1][0], s[2*c+1][1]); ph[2] = *(uint32_t*)&h;
                r0 = s[2*c+1][0] - __bfloat162float(h.x); r1 = s[2*c+1][1] - __bfloat162float(h.y);
                pl[2] = pack_bf16(r0, r1);
                h = __floats2bfloat162_rn(s[2*c+1][2], s[2*c+1][3]); ph[3] = *(uint32_t*)&h;
                r0 = s[2*c+1][2] - __bfloat162float(h.x); r1 = s[2*c+1][3] - __bfloat162float(h.y);
                pl[3] = pack_bf16(r0, r1);
            }
            #pragma unroll
            for (int jp = 0; jp < 8; jp++) {
                uint32_t va = vbase + c * 4096u + (((2u * jp + hcV) ^ m7) << 4);
                uint32_t bh[4], bl[4];
                ldsm_x4_t(bh, va + SM_V_HI);
                ldsm_x4_t(bl, va + SM_V_LO);
                mma_bf16(o[2*jp],   ph, bh[0], bh[1]);
                mma_bf16(o[2*jp],   ph, bl[0], bl[1]);
                mma_bf16(o[2*jp],   pl, bh[0], bh[1]);
                mma_bf16(o[2*jp+1], ph, bh[2], bh[3]);
                mma_bf16(o[2*jp+1], ph, bl[2], bl[3]);
                mma_bf16(o[2*jp+1], pl, bh[2], bh[3]);
            }
        }
    }

    // ---- epilogue ----
    float inv0 = 1.f / l0, inv1 = 1.f / l1;
    float* out0 = Out + (size_t)((size_t)b * SEQ + q0 + wr + g) * DIM;
    float* out1 = out0 + 8 * DIM;
    #pragma unroll
    for (int j = 0; j < 16; j++) {
        int col = 8 * j + 2 * t4;
        *(float2*)(out0 + col) = make_float2(o[j][0] * inv0, o[j][1] * inv0);
        *(float2*)(out1 + col) = make_float2(o[j][2] * inv1, o[j][3] * inv1);
    }
}

extern "C" void kernel_launch(void* const* d_in, const int* in_sizes, int n_in,
                              void* d_out, int out_size)
{
    const float* Q     = (const float*)d_in[0];
    const float* K     = (const float*)d_in[1];
    const float* V     = (const float*)d_in[2];
    const float* scale = (const float*)d_in[3];
    float* O = (float*)d_out;

    cudaFuncSetAttribute(attn_mma_kernel,
                         cudaFuncAttributeMaxDynamicSharedMemorySize, SM_TOTAL);
    dim3 grid(SEQ / BM, BATCH);
    attn_mma_kernel<<<grid, NTHREADS, SM_TOTAL>>>(Q, K, V, scale, O);
}

// round 5
// speedup vs baseline: 1.2909x; 1.2909x over previous
#include <cuda_runtime.h>
#include <cuda_bf16.h>
#include <cstdint>

#define BATCH 16
#define SEQ   2048
#define DIM   128
#define BM    128
#define BN    64
#define KTILES (SEQ / BN)
#define NTHREADS 256

// bf16 tiles: 256 B/row, XOR swizzle on 16B chunks.
#define SM_Q_HI 0
#define SM_Q_LO 32768
#define SM_K_HI 65536
#define SM_K_LO 81920
#define SM_V_HI 98304
#define SM_V_LO 114688
#define SM_SC   131072                     // scale [128][68] f32 (stride 272B)
#define SM_TOTAL (SM_SC + 128 * 68 * 4)    // 165888

__device__ __forceinline__ uint32_t smem_u32(const void* p) {
    uint32_t a;
    asm("{ .reg .u64 t; cvta.to.shared.u64 t, %1; cvt.u32.u64 %0, t; }" : "=r"(a) : "l"(p));
    return a;
}
__device__ __forceinline__ uint32_t swz(int r, int c4) {
    return (uint32_t)(r * 256 + ((((c4 >> 1) ^ (r & 7)) << 4) | ((c4 & 1) << 3)));
}
__device__ __forceinline__ void ldsm_x4(uint32_t* r, uint32_t a) {
    asm volatile("ldmatrix.sync.aligned.m8n8.x4.shared.b16 {%0,%1,%2,%3}, [%4];"
        : "=r"(r[0]), "=r"(r[1]), "=r"(r[2]), "=r"(r[3]) : "r"(a));
}
__device__ __forceinline__ void ldsm_x4_t(uint32_t* r, uint32_t a) {
    asm volatile("ldmatrix.sync.aligned.m8n8.x4.trans.shared.b16 {%0,%1,%2,%3}, [%4];"
        : "=r"(r[0]), "=r"(r[1]), "=r"(r[2]), "=r"(r[3]) : "r"(a));
}
__device__ __forceinline__ void mma_bf16(float* c, const uint32_t* a, uint32_t b0, uint32_t b1) {
    asm volatile("mma.sync.aligned.m16n8k16.row.col.f32.bf16.bf16.f32 "
        "{%0,%1,%2,%3}, {%4,%5,%6,%7}, {%8,%9}, {%0,%1,%2,%3};"
        : "+f"(c[0]), "+f"(c[1]), "+f"(c[2]), "+f"(c[3])
        : "r"(a[0]), "r"(a[1]), "r"(a[2]), "r"(a[3]), "r"(b0), "r"(b1));
}
__device__ __forceinline__ uint32_t pack_bf16(float lo, float hi) {
    __nv_bfloat162 t = __floats2bfloat162_rn(lo, hi);
    return *reinterpret_cast<uint32_t*>(&t);
}
__device__ __forceinline__ void cvt_split(float4 v, uint2& hi, uint2& lo) {
    __nv_bfloat162 h01 = __floats2bfloat162_rn(v.x, v.y);
    __nv_bfloat162 h23 = __floats2bfloat162_rn(v.z, v.w);
    float rx = v.x - __bfloat162float(h01.x);
    float ry = v.y - __bfloat162float(h01.y);
    float rz = v.z - __bfloat162float(h23.x);
    float rw = v.w - __bfloat162float(h23.y);
    __nv_bfloat162 l01 = __floats2bfloat162_rn(rx, ry);
    __nv_bfloat162 l23 = __floats2bfloat162_rn(rz, rw);
    hi = make_uint2(*reinterpret_cast<uint32_t*>(&h01), *reinterpret_cast<uint32_t*>(&h23));
    lo = make_uint2(*reinterpret_cast<uint32_t*>(&l01), *reinterpret_cast<uint32_t*>(&l23));
}
// FFMA-pipe exp (no MUFU), x <= 0; fexp(0) == 1.0f exactly
__device__ __forceinline__ float fexp(float x) {
    float t = fmaxf(x * 1.4426950408889634f, -126.0f);
    float z = __fadd_rn(t, 12582912.0f);
    int   n = __float_as_int(z) - 0x4B400000;
    float f = t - (z - 12582912.0f);
    float p = 0.0013333558f;
    p = fmaf(p, f, 0.0096181291f);
    p = fmaf(p, f, 0.0555041086f);
    p = fmaf(p, f, 0.2402265069f);
    p = fmaf(p, f, 0.6931471806f);
    p = fmaf(p, f, 1.0f);
    return __int_as_float(__float_as_int(p) + (n << 23));
}
__device__ __forceinline__ void cp_async16(uint32_t dst, const void* src) {
    asm volatile("cp.async.ca.shared.global [%0], [%1], 16;" :: "r"(dst), "l"(src));
}

__global__ __launch_bounds__(NTHREADS, 1)
void attn_mma_kernel(const float* __restrict__ Q, const float* __restrict__ K,
                     const float* __restrict__ V, const float* __restrict__ scale,
                     float* __restrict__ Out)
{
    extern __shared__ char smem[];
    const uint32_t sb = smem_u32(smem);
    float* scs = (float*)(smem + SM_SC);

    const int tid  = threadIdx.x;
    const int wid  = tid >> 5;
    const int lane = tid & 31;
    const int g    = lane >> 2;
    const int t4   = lane & 3;
    const int wr   = wid * 16;
    const int q0   = blockIdx.x * BM;
    const int b    = blockIdx.y;
    const int m7   = lane & 7;

    const float* Qb = Q + (size_t)b * SEQ * DIM;
    const float* Kb = K + (size_t)b * SEQ * DIM;
    const float* Vb = V + (size_t)b * SEQ * DIM;

    // ---- stage Q tile once: f32 -> bf16 hi/lo, swizzled ----
    for (int i = tid; i < BM * 32; i += NTHREADS) {
        int r = i >> 5, c4 = i & 31;
        float4 v = *(const float4*)(Qb + (size_t)(q0 + r) * DIM + c4 * 4);
        uint2 hi, lo; cvt_split(v, hi, lo);
        uint32_t so = swz(r, c4);
        *(uint2*)(smem + SM_Q_HI + so) = hi;
        *(uint2*)(smem + SM_Q_LO + so) = lo;
    }

    // per-lane ldmatrix bases
    const uint32_t hcA = (lane >> 4) & 1;
    const uint32_t hcB = (lane >> 3) & 1;
    const uint32_t hcV = (lane >> 4) & 1;
    const uint32_t qrow  = (uint32_t)(wr + m7 + ((lane >> 3) & 1) * 8);
    const uint32_t krowl = (uint32_t)(m7 + ((lane >> 4) & 1) * 8);
    const uint32_t vrowl = (uint32_t)(lane & 15);
    const uint32_t qbase = sb + qrow * 256;
    const uint32_t kbase = sb + krowl * 256;
    const uint32_t vbase = sb + vrowl * 256;

    float o[16][4];
    #pragma unroll
    for (int j = 0; j < 16; j++)
        { o[j][0] = 0.f; o[j][1] = 0.f; o[j][2] = 0.f; o[j][3] = 0.f; }
    float m0 = -1e30f, m1 = -1e30f, l0 = 0.f, l1 = 0.f;

    for (int kt = 0; kt < KTILES; kt++) {
        const int k0 = kt * BN;
        __syncthreads();

        // ---- scale tile via cp.async (hidden under convert + QK) ----
        #pragma unroll
        for (int u = 0; u < 8; u++) {
            int i = tid + u * NTHREADS;          // i < 128*16
            int r = i >> 4, c4 = i & 15;
            cp_async16(sb + SM_SC + (uint32_t)(r * 272 + c4 * 16),
                       scale + (size_t)(q0 + r) * SEQ + k0 + c4 * 4);
        }
        // ---- K, V tiles: f32 -> bf16 hi/lo, swizzled ----
        #pragma unroll
        for (int u = 0; u < 8; u++) {
            int i = tid + u * NTHREADS;          // i < 64*32
            int r = i >> 5, c4 = i & 31;
            float4 kv = *(const float4*)(Kb + (size_t)(k0 + r) * DIM + c4 * 4);
            float4 vv = *(const float4*)(Vb + (size_t)(k0 + r) * DIM + c4 * 4);
            uint2 hi, lo;
            uint32_t so = swz(r, c4);
            cvt_split(kv, hi, lo);
            *(uint2*)(smem + SM_K_HI + so) = hi;
            *(uint2*)(smem + SM_K_LO + so) = lo;
            cvt_split(vv, hi, lo);
            *(uint2*)(smem + SM_V_HI + so) = hi;
            *(uint2*)(smem + SM_V_LO + so) = lo;
        }
        asm volatile("cp.async.wait_all;" ::: "memory");
        __syncthreads();

        // ---- S = (Q K^T), bf16 3-product split; batched LDSM per kc ----
        float s[8][4];
        #pragma unroll
        for (int j = 0; j < 8; j++)
            { s[j][0] = 0.f; s[j][1] = 0.f; s[j][2] = 0.f; s[j][3] = 0.f; }

        #pragma unroll
        for (int kc = 0; kc < 8; kc++) {
            uint32_t aoff = ((2u * kc + hcA) ^ m7) << 4;
            uint32_t boff = ((2u * kc + hcB) ^ m7) << 4;
            uint32_t ah[4], al[4], bh[4][4], bl[4][4];
            ldsm_x4(ah, qbase + SM_Q_HI + aoff);
            ldsm_x4(al, qbase + SM_Q_LO + aoff);
            #pragma unroll
            for (int jp = 0; jp < 4; jp++) {
                uint32_t ka = kbase + jp * 4096u + boff;
                ldsm_x4(bh[jp], ka + SM_K_HI);
                ldsm_x4(bl[jp], ka + SM_K_LO);
            }
            #pragma unroll
            for (int jp = 0; jp < 4; jp++) {
                mma_bf16(s[2*jp],   ah, bh[jp][0], bh[jp][1]);
                mma_bf16(s[2*jp],   ah, bl[jp][0], bl[jp][1]);
                mma_bf16(s[2*jp],   al, bh[jp][0], bh[jp][1]);
                mma_bf16(s[2*jp+1], ah, bh[jp][2], bh[jp][3]);
                mma_bf16(s[2*jp+1], ah, bl[jp][2], bl[jp][3]);
                mma_bf16(s[2*jp+1], al, bh[jp][2], bh[jp][3]);
            }
        }

        // ---- scale multiply + online softmax ----
        const float* sc0 = scs + (wr + g) * 68;
        const float* sc1 = sc0 + 8 * 68;
        float mx0 = -1e30f, mx1 = -1e30f;
        #pragma unroll
        for (int j = 0; j < 8; j++) {
            float2 a = *(const float2*)(sc0 + 8 * j + 2 * t4);
            float2 c = *(const float2*)(sc1 + 8 * j + 2 * t4);
            s[j][0] *= a.x; s[j][1] *= a.y;
            s[j][2] *= c.x; s[j][3] *= c.y;
            mx0 = fmaxf(mx0, fmaxf(s[j][0], s[j][1]));
            mx1 = fmaxf(mx1, fmaxf(s[j][2], s[j][3]));
        }
        mx0 = fmaxf(mx0, __shfl_xor_sync(0xffffffffu, mx0, 1));
        mx0 = fmaxf(mx0, __shfl_xor_sync(0xffffffffu, mx0, 2));
        mx1 = fmaxf(mx1, __shfl_xor_sync(0xffffffffu, mx1, 1));
        mx1 = fmaxf(mx1, __shfl_xor_sync(0xffffffffu, mx1, 2));

        float mn0 = fmaxf(m0, mx0), mn1 = fmaxf(m1, mx1);
        float a0 = fexp(m0 - mn0),  a1 = fexp(m1 - mn1);
        float sum0 = 0.f, sum1 = 0.f;
        #pragma unroll
        for (int j = 0; j < 8; j++) {
            s[j][0] = fexp(s[j][0] - mn0); sum0 += s[j][0];
            s[j][1] = fexp(s[j][1] - mn0); sum0 += s[j][1];
            s[j][2] = fexp(s[j][2] - mn1); sum1 += s[j][2];
            s[j][3] = fexp(s[j][3] - mn1); sum1 += s[j][3];
        }
        sum0 += __shfl_xor_sync(0xffffffffu, sum0, 1);
        sum0 += __shfl_xor_sync(0xffffffffu, sum0, 2);
        sum1 += __shfl_xor_sync(0xffffffffu, sum1, 1);
        sum1 += __shfl_xor_sync(0xffffffffu, sum1, 2);
        l0 = l0 * a0 + sum0; m0 = mn0;
        l1 = l1 * a1 + sum1; m1 = mn1;
        if (a0 != 1.0f || a1 != 1.0f) {
            #pragma unroll
            for (int j = 0; j < 16; j++) {
                o[j][0] *= a0; o[j][1] *= a0;
                o[j][2] *= a1; o[j][3] *= a1;
            }
        }

        // ---- O += P V, bf16 3-product split; batched LDSM per jp-pair ----
        #pragma unroll
        for (int c = 0; c < 4; c++) {
            uint32_t ph[4], pl[4];
            {
                __nv_bfloat162 h; float r0, r1;
                h = __floats2bfloat162_rn(s[2*c][0], s[2*c][1]); ph[0] = *(uint32_t*)&h;
                r0 = s[2*c][0] - __bfloat162float(h.x); r1 = s[2*c][1] - __bfloat162float(h.y);
                pl[0] = pack_bf16(r0, r1);
                h = __floats2bfloat162_rn(s[2*c][2], s[2*c][3]); ph[1] = *(uint32_t*)&h;
                r0 = s[2*c][2] - __bfloat162float(h.x); r1 = s[2*c][3] - __bfloat162float(h.y);
                pl[1] = pack_bf16(r0, r1);
                h = __floats2bfloat162_rn(s[2*c+1][0], s[2*c+1][1]); ph[2] = *(uint32_t*)&h;
                r0 = s[2*c+1][0] - __bfloat162float(h.x); r1 = s[2*c+1][1] - __bfloat162float(h.y);
                pl[2] = pack_bf16(r0, r1);
                h = __floats2bfloat162_rn(s[2*c+1][2], s[2*c+1][3]); ph[3] = *(uint32_t*)&h;
                r0 = s[2*c+1][2] - __bfloat162float(h.x); r1 = s[2*c+1][3] - __bfloat162float(h.y);
                pl[3] = pack_bf16(r0, r1);
            }
            #pragma unroll
            for (int jq = 0; jq < 4; jq++) {            // jp pairs: (2jq, 2jq+1)
                uint32_t bh[2][4], bl[2][4];
                #pragma unroll
                for (int h2 = 0; h2 < 2; h2++) {
                    int jp = 2 * jq + h2;
                    uint32_t va = vbase + c * 4096u + (((2u * jp + hcV) ^ m7) << 4);
                    ldsm_x4_t(bh[h2], va + SM_V_HI);
                    ldsm_x4_t(bl[h2], va + SM_V_LO);
                }
                #pragma unroll
                for (int h2 = 0; h2 < 2; h2++) {
                    int jp = 2 * jq + h2;
                    mma_bf16(o[2*jp],   ph, bh[h2][0], bh[h2][1]);
                    mma_bf16(o[2*jp],   ph, bl[h2][0], bl[h2][1]);
                    mma_bf16(o[2*jp],   pl, bh[h2][0], bh[h2][1]);
                    mma_bf16(o[2*jp+1], ph, bh[h2][2], bh[h2][3]);
                    mma_bf16(o[2*jp+1], ph, bl[h2][2], bl[h2][3]);
                    mma_bf16(o[2*jp+1], pl, bh[h2][2], bh[h2][3]);
                }
            }
        }
    }

    // ---- epilogue ----
    float inv0 = 1.f / l0, inv1 = 1.f / l1;
    float* out0 = Out + (size_t)((size_t)b * SEQ + q0 + wr + g) * DIM;
    float* out1 = out0 + 8 * DIM;
    #pragma unroll
    for (int j = 0; j < 16; j++) {
        int col = 8 * j + 2 * t4;
        *(float2*)(out0 + col) = make_float2(o[j][0] * inv0, o[j][1] * inv0);
        *(float2*)(out1 + col) = make_float2(o[j][2] * inv1, o[j][3] * inv1);
    }
}

extern "C" void kernel_launch(void* const* d_in, const int* in_sizes, int n_in,
                              void* d_out, int out_size)
{
    const float* Q     = (const float*)d_in[0];
    const float* K     = (const float*)d_in[1];
    const float* V     = (const float*)d_in[2];
    const float* scale = (const float*)d_in[3];
    float* O = (float*)d_out;

    cudaFuncSetAttribute(attn_mma_kernel,
                         cudaFuncAttributeMaxDynamicSharedMemorySize, SM_TOTAL);
    dim3 grid(SEQ / BM, BATCH);
    attn_mma_kernel<<<grid, NTHREADS, SM_TOTAL>>>(Q, K, V, scale, O);
}

// round 6
// speedup vs baseline: 1.4047x; 1.0882x over previous
#include <cuda_runtime.h>
#include <cuda_bf16.h>
#include <cstdint>

#define BATCH 16
#define SEQ   2048
#define DIM   128
#define BM    128
#define BN    64
#define KTILES (SEQ / BN)
#define NTHREADS 256

// Pre-converted K/V tiles in gmem: per (b,kt) a 64 KB blob laid out exactly as
// the SMEM stage buffer: [K_HI 16K][K_LO 16K][V_HI 16K][V_LO 16K], each tile
// 64 rows x 256 B with the XOR-16B-chunk swizzle baked in.
#define KV_TILE_BYTES 65536
__device__ unsigned char g_kv[(size_t)BATCH * KTILES * KV_TILE_BYTES];  // 32 MB

// SMEM: two 64 KB stage buffers + Q hi/lo tiles
#define SM_STAGE0 0
#define SM_STAGE1 65536
#define SM_Q_HI   131072
#define SM_Q_LO   163840
#define SM_TOTAL  196608

#define OFF_KHI 0
#define OFF_KLO 16384
#define OFF_VHI 32768
#define OFF_VLO 49152

__device__ __forceinline__ uint32_t smem_u32(const void* p) {
    uint32_t a;
    asm("{ .reg .u64 t; cvta.to.shared.u64 t, %1; cvt.u32.u64 %0, t; }" : "=r"(a) : "l"(p));
    return a;
}
__device__ __forceinline__ uint32_t swz(int r, int c4) {
    return (uint32_t)(r * 256 + ((((c4 >> 1) ^ (r & 7)) << 4) | ((c4 & 1) << 3)));
}
__device__ __forceinline__ void ldsm_x4(uint32_t* r, uint32_t a) {
    asm volatile("ldmatrix.sync.aligned.m8n8.x4.shared.b16 {%0,%1,%2,%3}, [%4];"
        : "=r"(r[0]), "=r"(r[1]), "=r"(r[2]), "=r"(r[3]) : "r"(a));
}
__device__ __forceinline__ void ldsm_x4_t(uint32_t* r, uint32_t a) {
    asm volatile("ldmatrix.sync.aligned.m8n8.x4.trans.shared.b16 {%0,%1,%2,%3}, [%4];"
        : "=r"(r[0]), "=r"(r[1]), "=r"(r[2]), "=r"(r[3]) : "r"(a));
}
__device__ __forceinline__ void mma_bf16(float* c, const uint32_t* a, uint32_t b0, uint32_t b1) {
    asm volatile("mma.sync.aligned.m16n8k16.row.col.f32.bf16.bf16.f32 "
        "{%0,%1,%2,%3}, {%4,%5,%6,%7}, {%8,%9}, {%0,%1,%2,%3};"
        : "+f"(c[0]), "+f"(c[1]), "+f"(c[2]), "+f"(c[3])
        : "r"(a[0]), "r"(a[1]), "r"(a[2]), "r"(a[3]), "r"(b0), "r"(b1));
}
__device__ __forceinline__ uint32_t pack_bf16(float lo, float hi) {
    __nv_bfloat162 t = __floats2bfloat162_rn(lo, hi);
    return *reinterpret_cast<uint32_t*>(&t);
}
__device__ __forceinline__ void cvt_split(float4 v, uint2& hi, uint2& lo) {
    __nv_bfloat162 h01 = __floats2bfloat162_rn(v.x, v.y);
    __nv_bfloat162 h23 = __floats2bfloat162_rn(v.z, v.w);
    float rx = v.x - __bfloat162float(h01.x);
    float ry = v.y - __bfloat162float(h01.y);
    float rz = v.z - __bfloat162float(h23.x);
    float rw = v.w - __bfloat162float(h23.y);
    __nv_bfloat162 l01 = __floats2bfloat162_rn(rx, ry);
    __nv_bfloat162 l23 = __floats2bfloat162_rn(rz, rw);
    hi = make_uint2(*reinterpret_cast<uint32_t*>(&h01), *reinterpret_cast<uint32_t*>(&h23));
    lo = make_uint2(*reinterpret_cast<uint32_t*>(&l01), *reinterpret_cast<uint32_t*>(&l23));
}
__device__ __forceinline__ float ex2f(float x) {
    float y;
    asm("ex2.approx.ftz.f32 %0, %1;" : "=f"(y) : "f"(x));
    return y;
}
__device__ __forceinline__ void cp_async16(uint32_t dst, const void* src) {
    asm volatile("cp.async.ca.shared.global [%0], [%1], 16;" :: "r"(dst), "l"(src));
}

// ---------------- pre-pass: K,V f32 -> swizzled bf16 hi/lo tiles ----------------
__global__ __launch_bounds__(256)
void kv_prepass(const float* __restrict__ K, const float* __restrict__ V)
{
    int i = blockIdx.x * 256 + threadIdx.x;          // 0 .. 16*2048*32-1
    int b   = i >> 16;
    int rem = i & 65535;
    int rg  = rem >> 5;                              // global row 0..2047
    int c4  = rem & 31;
    int kt  = rg >> 6;
    int r   = rg & 63;

    size_t src = ((size_t)b * SEQ + rg) * DIM + c4 * 4;
    float4 kv = *(const float4*)(K + src);
    float4 vv = *(const float4*)(V + src);

    unsigned char* dst = g_kv + (size_t)(b * KTILES + kt) * KV_TILE_BYTES;
    uint32_t so = swz(r, c4);
    uint2 hi, lo;
    cvt_split(kv, hi, lo);
    *(uint2*)(dst + OFF_KHI + so) = hi;
    *(uint2*)(dst + OFF_KLO + so) = lo;
    cvt_split(vv, hi, lo);
    *(uint2*)(dst + OFF_VHI + so) = hi;
    *(uint2*)(dst + OFF_VLO + so) = lo;
}

// ---------------- main kernel ----------------
__global__ __launch_bounds__(NTHREADS, 1)
void attn_mma_kernel(const float* __restrict__ Q, const float* __restrict__ scale,
                     float* __restrict__ Out)
{
    extern __shared__ char smem[];
    const uint32_t sb = smem_u32(smem);

    const int tid  = threadIdx.x;
    const int wid  = tid >> 5;
    const int lane = tid & 31;
    const int g    = lane >> 2;
    const int t4   = lane & 3;
    const int wr   = wid * 16;
    const int q0   = blockIdx.x * BM;
    const int b    = blockIdx.y;
    const int m7   = lane & 7;
    const float L2E = 1.4426950408889634f;

    const float* Qb = Q + (size_t)b * SEQ * DIM;
    const unsigned char* gkv = g_kv + (size_t)b * KTILES * KV_TILE_BYTES;

    // ---- prologue: prefetch tile 0 into stage 0 ----
    {
        const unsigned char* srcb = gkv;
        #pragma unroll
        for (int u = 0; u < 16; u++) {
            int idx = tid + u * NTHREADS;
            cp_async16(sb + SM_STAGE0 + idx * 16, srcb + idx * 16);
        }
        asm volatile("cp.async.commit_group;" ::: "memory");
    }

    // ---- stage Q tile once: f32 -> bf16 hi/lo, swizzled ----
    for (int i = tid; i < BM * 32; i += NTHREADS) {
        int r = i >> 5, c4 = i & 31;
        float4 v = *(const float4*)(Qb + (size_t)(q0 + r) * DIM + c4 * 4);
        uint2 hi, lo; cvt_split(v, hi, lo);
        uint32_t so = swz(r, c4);
        *(uint2*)(smem + SM_Q_HI + so) = hi;
        *(uint2*)(smem + SM_Q_LO + so) = lo;
    }

    // per-lane ldmatrix bases
    const uint32_t hcA = (lane >> 4) & 1;
    const uint32_t hcB = (lane >> 3) & 1;
    const uint32_t hcV = (lane >> 4) & 1;
    const uint32_t qrow  = (uint32_t)(wr + m7 + ((lane >> 3) & 1) * 8);
    const uint32_t krowl = (uint32_t)(m7 + ((lane >> 4) & 1) * 8);
    const uint32_t vrowl = (uint32_t)(lane & 15);
    const uint32_t qbase = sb + SM_Q_HI + qrow * 256;

    // scale row pointers for this thread
    const float* sp0 = scale + (size_t)(q0 + wr + g) * SEQ + 2 * t4;
    const float* sp1 = sp0 + 8 * SEQ;

    float o[16][4];
    #pragma unroll
    for (int j = 0; j < 16; j++)
        { o[j][0] = 0.f; o[j][1] = 0.f; o[j][2] = 0.f; o[j][3] = 0.f; }
    float m0 = -1e30f, m1 = -1e30f, l0 = 0.f, l1 = 0.f;

    for (int kt = 0; kt < KTILES; kt++) {
        __syncthreads();                       // prior iteration's reads done

        // ---- prefetch tile kt+1, wait for tile kt ----
        if (kt + 1 < KTILES) {
            const unsigned char* srcb = gkv + (size_t)(kt + 1) * KV_TILE_BYTES;
            uint32_t dstb = sb + ((kt + 1) & 1 ? SM_STAGE1 : SM_STAGE0);
            #pragma unroll
            for (int u = 0; u < 16; u++) {
                int idx = tid + u * NTHREADS;
                cp_async16(dstb + idx * 16, srcb + idx * 16);
            }
            asm volatile("cp.async.commit_group;" ::: "memory");
            asm volatile("cp.async.wait_group 1;" ::: "memory");
        } else {
            asm volatile("cp.async.wait_group 0;" ::: "memory");
        }
        __syncthreads();                       // tile kt visible to all

        const uint32_t stg = sb + ((kt & 1) ? SM_STAGE1 : SM_STAGE0);
        const uint32_t kbase = stg + OFF_KHI + krowl * 256;
        const uint32_t vbase = stg + OFF_VHI + vrowl * 256;

        // ---- scale rows -> registers (L2 hits, hidden under QK), fold log2e ----
        float2 scA[8], scB[8];
        #pragma unroll
        for (int j = 0; j < 8; j++) {
            float2 a = __ldg((const float2*)(sp0 + (size_t)kt * BN + 8 * j));
            float2 c = __ldg((const float2*)(sp1 + (size_t)kt * BN + 8 * j));
            scA[j] = make_float2(a.x * L2E, a.y * L2E);
            scB[j] = make_float2(c.x * L2E, c.y * L2E);
        }

        // ---- S = (Q K^T), bf16 3-product split ----
        float s[8][4];
        #pragma unroll
        for (int j = 0; j < 8; j++)
            { s[j][0] = 0.f; s[j][1] = 0.f; s[j][2] = 0.f; s[j][3] = 0.f; }

        #pragma unroll
        for (int kc = 0; kc < 8; kc++) {
            uint32_t aoff = ((2u * kc + hcA) ^ m7) << 4;
            uint32_t boff = ((2u * kc + hcB) ^ m7) << 4;
            uint32_t ah[4], al[4], bh[4][4], bl[4][4];
            ldsm_x4(ah, qbase + aoff);
            ldsm_x4(al, qbase + 32768 + aoff);
            #pragma unroll
            for (int jp = 0; jp < 4; jp++) {
                uint32_t ka = kbase + jp * 4096u + boff;
                ldsm_x4(bh[jp], ka);
                ldsm_x4(bl[jp], ka + 16384);
            }
            #pragma unroll
            for (int jp = 0; jp < 4; jp++) {
                mma_bf16(s[2*jp],   ah, bh[jp][0], bh[jp][1]);
                mma_bf16(s[2*jp],   ah, bl[jp][0], bl[jp][1]);
                mma_bf16(s[2*jp],   al, bh[jp][0], bh[jp][1]);
                mma_bf16(s[2*jp+1], ah, bh[jp][2], bh[jp][3]);
                mma_bf16(s[2*jp+1], ah, bl[jp][2], bl[jp][3]);
                mma_bf16(s[2*jp+1], al, bh[jp][2], bh[jp][3]);
            }
        }

        // ---- scale (log2 domain) + online softmax via MUFU ex2 ----
        float mx0 = -1e30f, mx1 = -1e30f;
        #pragma unroll
        for (int j = 0; j < 8; j++) {
            s[j][0] *= scA[j].x; s[j][1] *= scA[j].y;
            s[j][2] *= scB[j].x; s[j][3] *= scB[j].y;
            mx0 = fmaxf(mx0, fmaxf(s[j][0], s[j][1]));
            mx1 = fmaxf(mx1, fmaxf(s[j][2], s[j][3]));
        }
        mx0 = fmaxf(mx0, __shfl_xor_sync(0xffffffffu, mx0, 1));
        mx0 = fmaxf(mx0, __shfl_xor_sync(0xffffffffu, mx0, 2));
        mx1 = fmaxf(mx1, __shfl_xor_sync(0xffffffffu, mx1, 1));
        mx1 = fmaxf(mx1, __shfl_xor_sync(0xffffffffu, mx1, 2));

        float mn0 = fmaxf(m0, mx0), mn1 = fmaxf(m1, mx1);
        float a0 = ex2f(m0 - mn0),  a1 = ex2f(m1 - mn1);
        float sum0 = 0.f, sum1 = 0.f;
        #pragma unroll
        for (int j = 0; j < 8; j++) {
            s[j][0] = ex2f(s[j][0] - mn0); sum0 += s[j][0];
            s[j][1] = ex2f(s[j][1] - mn0); sum0 += s[j][1];
            s[j][2] = ex2f(s[j][2] - mn1); sum1 += s[j][2];
            s[j][3] = ex2f(s[j][3] - mn1); sum1 += s[j][3];
        }
        sum0 += __shfl_xor_sync(0xffffffffu, sum0, 1);
        sum0 += __shfl_xor_sync(0xffffffffu, sum0, 2);
        sum1 += __shfl_xor_sync(0xffffffffu, sum1, 1);
        sum1 += __shfl_xor_sync(0xffffffffu, sum1, 2);
        l0 = l0 * a0 + sum0; m0 = mn0;
        l1 = l1 * a1 + sum1; m1 = mn1;
        if (a0 != 1.0f || a1 != 1.0f) {
            #pragma unroll
            for (int j = 0; j < 16; j++) {
                o[j][0] *= a0; o[j][1] *= a0;
                o[j][2] *= a1; o[j][3] *= a1;
            }
        }

        // ---- O += P V, bf16 3-product split ----
        #pragma unroll
        for (int c = 0; c < 4; c++) {
            uint32_t ph[4], pl[4];
            {
                __nv_bfloat162 h; float r0, r1;
                h = __floats2bfloat162_rn(s[2*c][0], s[2*c][1]); ph[0] = *(uint32_t*)&h;
                r0 = s[2*c][0] - __bfloat162float(h.x); r1 = s[2*c][1] - __bfloat162float(h.y);
                pl[0] = pack_bf16(r0, r1);
                h = __floats2bfloat162_rn(s[2*c][2], s[2*c][3]); ph[1] = *(uint32_t*)&h;
                r0 = s[2*c][2] - __bfloat162float(h.x); r1 = s[2*c][3] - __bfloat162float(h.y);
                pl[1] = pack_bf16(r0, r1);
                h = __floats2bfloat162_rn(s[2*c+1][0], s[2*c+1][1]); ph[2] = *(uint32_t*)&h;
                r0 = s[2*c+1][0] - __bfloat162float(h.x); r1 = s[2*c+1][1] - __bfloat162float(h.y);
                pl[2] = pack_bf16(r0, r1);
                h = __floats2bfloat162_rn(s[2*c+1][2], s[2*c+1][3]); ph[3] = *(uint32_t*)&h;
                r0 = s[2*c+1][2] - __bfloat162float(h.x); r1 = s[2*c+1][3] - __bfloat162float(h.y);
                pl[3] = pack_bf16(r0, r1);
            }
            #pragma unroll
            for (int jq = 0; jq < 4; jq++) {
                uint32_t bh[2][4], bl[2][4];
                #pragma unroll
                for (int h2 = 0; h2 < 2; h2++) {
                    int jp = 2 * jq + h2;
                    uint32_t va = vbase + c * 4096u + (((2u * jp + hcV) ^ m7) << 4);
                    ldsm_x4_t(bh[h2], va);
                    ldsm_x4_t(bl[h2], va + 16384);
                }
                #pragma unroll
                for (int h2 = 0; h2 < 2; h2++) {
                    int jp = 2 * jq + h2;
                    mma_bf16(o[2*jp],   ph, bh[h2][0], bh[h2][1]);
                    mma_bf16(o[2*jp],   ph, bl[h2][0], bl[h2][1]);
                    mma_bf16(o[2*jp],   pl, bh[h2][0], bh[h2][1]);
                    mma_bf16(o[2*jp+1], ph, bh[h2][2], bh[h2][3]);
                    mma_bf16(o[2*jp+1], ph, bl[h2][2], bl[h2][3]);
                    mma_bf16(o[2*jp+1], pl, bh[h2][2], bh[h2][3]);
                }
            }
        }
    }

    // ---- epilogue ----
    float inv0 = 1.f / l0, inv1 = 1.f / l1;
    float* out0 = Out + (size_t)((size_t)b * SEQ + q0 + wr + g) * DIM;
    float* out1 = out0 + 8 * DIM;
    #pragma unroll
    for (int j = 0; j < 16; j++) {
        int col = 8 * j + 2 * t4;
        *(float2*)(out0 + col) = make_float2(o[j][0] * inv0, o[j][1] * inv0);
        *(float2*)(out1 + col) = make_float2(o[j][2] * inv1, o[j][3] * inv1);
    }
}

extern "C" void kernel_launch(void* const* d_in, const int* in_sizes, int n_in,
                              void* d_out, int out_size)
{
    const float* Q     = (const float*)d_in[0];
    const float* K     = (const float*)d_in[1];
    const float* V     = (const float*)d_in[2];
    const float* scale = (const float*)d_in[3];
    float* O = (float*)d_out;

    kv_prepass<<<(BATCH * SEQ * 32) / 256, 256>>>(K, V);

    cudaFuncSetAttribute(attn_mma_kernel,
                         cudaFuncAttributeMaxDynamicSharedMemorySize, SM_TOTAL);
    dim3 grid(SEQ / BM, BATCH);
    attn_mma_kernel<<<grid, NTHREADS, SM_TOTAL>>>(Q, scale, O);
}